// round 1
// baseline (speedup 1.0000x reference)
#include <cuda_runtime.h>
#include <math.h>

// NeRF-style renderer: B=1, H=W=200, FOCAL=300, NEAR=2, FAR=6, S=128, F=8.
// Inputs (metadata order):
//  0 positions[3], 1 forwards[3], 2 ups[3], 3 normal[128],
//  4 Wf[3*8], 5 bf[8], 6 Wd[11], 7 bd[1], 8 Wc[11*3], 9 bc[3]
// Output: color_map [200*200*3] followed by depth_map [200*200] (fp32).

#define H 200
#define W 200
#define NPIX (H * W)
#define S 128
#define F 8
#define FOCAL 300.0f
#define NEARP 2.0f
#define FARP 6.0f

__global__ __launch_bounds__(128, 16)
void render_kernel(const float* __restrict__ positions,
                   const float* __restrict__ forwards,
                   const float* __restrict__ ups,
                   const float* __restrict__ normal,
                   const float* __restrict__ Wf,
                   const float* __restrict__ bf,
                   const float* __restrict__ Wd,
                   const float* __restrict__ bd,
                   const float* __restrict__ Wc,
                   const float* __restrict__ bc,
                   float* __restrict__ out)
{
    // ---- shared staging of tiny operands ----
    __shared__ float s_t[S];       // sample distances
    __shared__ float s_dl[S];      // raw deltas (pre |dir| scale)
    __shared__ float s_Wf[3][F];
    __shared__ float s_WdF[F];     // feature part of density weights
    __shared__ float s_negWcF[F][3]; // negated feature color weights
    __shared__ float s_cam[12];    // right(3), up(3), fwd(3), pos(3)
    __shared__ float s_Wd3[3];     // pos part of density weights
    __shared__ float s_Wc3[3][3];  // dir part of color weights
    __shared__ float s_bc[3];
    __shared__ float s_bf[F];
    __shared__ float s_bd;

    const int tid = threadIdx.x;

    if (tid < S) {
        float n0 = normal[tid];
        s_t[tid] = NEARP + n0 * (FARP - NEARP);
        if (tid < S - 1) {
            s_dl[tid] = (normal[tid + 1] - n0) * (FARP - NEARP);
        } else {
            s_dl[tid] = 1e10f;
        }
    }
    if (tid < 24) s_Wf[tid / F][tid % F] = Wf[tid];
    if (tid >= 32 && tid < 32 + F) {
        int j = tid - 32;
        s_WdF[j] = Wd[3 + j];
        s_bf[j] = bf[j];
    }
    if (tid >= 40 && tid < 40 + 24) {
        int k = tid - 40;        // k = j*3 + i over feature color weights
        s_negWcF[k / 3][k % 3] = -Wc[(3 + k / 3) * 3 + (k % 3)];
    }
    if (tid == 0) {
        float ux = ups[0], uy = ups[1], uz = ups[2];
        float fx = forwards[0], fy = forwards[1], fz = forwards[2];
        // right = cross(ups, forwards)
        s_cam[0] = uy * fz - uz * fy;
        s_cam[1] = uz * fx - ux * fz;
        s_cam[2] = ux * fy - uy * fx;
        s_cam[3] = ux; s_cam[4] = uy; s_cam[5] = uz;
        s_cam[6] = fx; s_cam[7] = fy; s_cam[8] = fz;
        s_cam[9] = positions[0]; s_cam[10] = positions[1]; s_cam[11] = positions[2];
        s_Wd3[0] = Wd[0]; s_Wd3[1] = Wd[1]; s_Wd3[2] = Wd[2];
        s_bd = bd[0];
        #pragma unroll
        for (int j = 0; j < 3; j++) {
            s_bc[j] = bc[j];
            #pragma unroll
            for (int i = 0; i < 3; i++) s_Wc3[j][i] = Wc[j * 3 + i];
        }
    }
    __syncthreads();

    const int pix = blockIdx.x * blockDim.x + tid;
    if (pix >= NPIX) return;

    const int h = pix / W;
    const int w = pix - h * W;

    // dl = [ (h - 99.5)/300, -(w - 99.5)/300, 1 ]
    const float a = ((float)h - (H * 0.5f - 0.5f)) * (1.0f / FOCAL);
    const float b = -((float)w - (W * 0.5f - 0.5f)) * (1.0f / FOCAL);

    const float dx = a * s_cam[0] + b * s_cam[3] + s_cam[6];
    const float dy = a * s_cam[1] + b * s_cam[4] + s_cam[7];
    const float dz = a * s_cam[2] + b * s_cam[5] + s_cam[8];
    const float dn = sqrtf(dx * dx + dy * dy + dz * dz);

    const float px = s_cam[9], py = s_cam[10], pz = s_cam[11];

    // per-pixel projections (hoisted out of the sample loop)
    float dirF[F], baseF[F];
    #pragma unroll
    for (int j = 0; j < F; j++) {
        dirF[j]  = dx * s_Wf[0][j] + dy * s_Wf[1][j] + dz * s_Wf[2][j];
        baseF[j] = px * s_Wf[0][j] + py * s_Wf[1][j] + pz * s_Wf[2][j] + s_bf[j];
    }
    const float dird  = dx * s_Wd3[0] + dy * s_Wd3[1] + dz * s_Wd3[2];
    const float based = px * s_Wd3[0] + py * s_Wd3[1] + pz * s_Wd3[2] + s_bd;

    float negBaseC[3];
    #pragma unroll
    for (int i = 0; i < 3; i++)
        negBaseC[i] = -(dx * s_Wc3[0][i] + dy * s_Wc3[1][i] + dz * s_Wc3[2][i] + s_bc[i]);

    float T = 1.0f;
    float c0 = 0.0f, c1 = 0.0f, c2 = 0.0f, depth = 0.0f;

    #pragma unroll 4
    for (int s = 0; s < S; s++) {
        const float t = s_t[s];

        float f[F];
        #pragma unroll
        for (int j = 0; j < F; j++)
            f[j] = fmaxf(fmaf(t, dirF[j], baseF[j]), 0.0f);

        float d = fmaf(t, dird, based);
        #pragma unroll
        for (int j = 0; j < F; j++)
            d = fmaf(f[j], s_WdF[j], d);
        d = fmaxf(d, 0.0f);

        // alpha compositing via transmittance: Tn = T*exp(-d*delta), w = T - Tn
        const float e  = __expf(-d * (s_dl[s] * dn));
        const float Tn = T * e;
        const float wgt = T - Tn;
        T = Tn;

        float x0 = negBaseC[0], x1 = negBaseC[1], x2 = negBaseC[2];
        #pragma unroll
        for (int j = 0; j < F; j++) {
            x0 = fmaf(f[j], s_negWcF[j][0], x0);
            x1 = fmaf(f[j], s_negWcF[j][1], x1);
            x2 = fmaf(f[j], s_negWcF[j][2], x2);
        }
        const float g0 = 1.0f / (1.0f + __expf(x0));
        const float g1 = 1.0f / (1.0f + __expf(x1));
        const float g2 = 1.0f / (1.0f + __expf(x2));

        c0 = fmaf(wgt, g0, c0);
        c1 = fmaf(wgt, g1, c1);
        c2 = fmaf(wgt, g2, c2);
        depth += wgt;
    }

    out[pix * 3 + 0] = c0;
    out[pix * 3 + 1] = c1;
    out[pix * 3 + 2] = c2;
    out[NPIX * 3 + pix] = depth;
}

extern "C" void kernel_launch(void* const* d_in, const int* in_sizes, int n_in,
                              void* d_out, int out_size)
{
    const float* positions = (const float*)d_in[0];
    const float* forwards  = (const float*)d_in[1];
    const float* ups       = (const float*)d_in[2];
    const float* normal    = (const float*)d_in[3];
    const float* Wf        = (const float*)d_in[4];
    const float* bf        = (const float*)d_in[5];
    const float* Wd        = (const float*)d_in[6];
    const float* bd        = (const float*)d_in[7];
    const float* Wc        = (const float*)d_in[8];
    const float* bc        = (const float*)d_in[9];
    float* out = (float*)d_out;

    const int threads = 128;
    const int blocks = (NPIX + threads - 1) / threads;
    render_kernel<<<blocks, threads>>>(positions, forwards, ups, normal,
                                       Wf, bf, Wd, bd, Wc, bc, out);
}

// round 3
// speedup vs baseline: 2.1630x; 2.1630x over previous
#include <cuda_runtime.h>
#include <math.h>

// NeRF-style renderer: B=1, H=W=200, FOCAL=300, NEAR=2, FAR=6, S=128, F=8.
// 4 threads per pixel, each composites a 32-sample segment; exact segmented
// combine via warp shuffles (width-4 groups).
// Output: color_map [200*200*3] then depth_map [200*200] (fp32).

#define H 200
#define W 200
#define NPIX (H * W)
#define S 128
#define F 8
#define SEG 4                 // threads per pixel
#define SPT (S / SEG)         // samples per thread = 32
#define FOCAL 300.0f
#define NEARP 2.0f
#define FARP 6.0f

__global__ __launch_bounds__(128, 16)
void render_kernel(const float* __restrict__ positions,
                   const float* __restrict__ forwards,
                   const float* __restrict__ ups,
                   const float* __restrict__ normal,
                   const float* __restrict__ Wf,
                   const float* __restrict__ bf,
                   const float* __restrict__ Wd,
                   const float* __restrict__ bd,
                   const float* __restrict__ Wc,
                   const float* __restrict__ bc,
                   float* __restrict__ out)
{
    // ---- shared staging ----
    // t/delta stored transposed: sample s = q*SPT + i lives at [i*SEG + q]
    // so the 4 segment-threads of a warp read 4 consecutive banks.
    __shared__ float s_t[S];
    __shared__ float s_dl[S];
    __shared__ float s_Wf[3][F];
    __shared__ float s_WdF[F];
    __shared__ float s_negWcF[F][3];
    __shared__ float s_cam[12];    // right(3), up(3), fwd(3), pos(3)
    __shared__ float s_Wd3[3];
    __shared__ float s_Wc3[3][3];
    __shared__ float s_bc[3];
    __shared__ float s_bf[F];
    __shared__ float s_bd;

    const int tid = threadIdx.x;

    if (tid < S) {
        float n0 = normal[tid];
        int xi = (tid % SPT) * SEG + (tid / SPT);   // transposed slot
        s_t[xi] = NEARP + n0 * (FARP - NEARP);
        s_dl[xi] = (tid < S - 1) ? (normal[tid + 1] - n0) * (FARP - NEARP)
                                 : 1e10f;
    }
    if (tid < 24) s_Wf[tid / F][tid % F] = Wf[tid];
    if (tid >= 32 && tid < 32 + F) {
        int j = tid - 32;
        s_WdF[j] = Wd[3 + j];
        s_bf[j] = bf[j];
    }
    if (tid >= 40 && tid < 40 + 24) {
        int k = tid - 40;
        s_negWcF[k / 3][k % 3] = -Wc[(3 + k / 3) * 3 + (k % 3)];
    }
    if (tid == 0) {
        float ux = ups[0], uy = ups[1], uz = ups[2];
        float fx = forwards[0], fy = forwards[1], fz = forwards[2];
        s_cam[0] = uy * fz - uz * fy;
        s_cam[1] = uz * fx - ux * fz;
        s_cam[2] = ux * fy - uy * fx;
        s_cam[3] = ux; s_cam[4] = uy; s_cam[5] = uz;
        s_cam[6] = fx; s_cam[7] = fy; s_cam[8] = fz;
        s_cam[9] = positions[0]; s_cam[10] = positions[1]; s_cam[11] = positions[2];
        s_Wd3[0] = Wd[0]; s_Wd3[1] = Wd[1]; s_Wd3[2] = Wd[2];
        s_bd = bd[0];
        #pragma unroll
        for (int j = 0; j < 3; j++) {
            s_bc[j] = bc[j];
            #pragma unroll
            for (int i = 0; i < 3; i++) s_Wc3[j][i] = Wc[j * 3 + i];
        }
    }
    __syncthreads();

    const int gtid = blockIdx.x * blockDim.x + tid;   // 160,000 threads exactly
    const int pix = gtid >> 2;
    const int q = gtid & 3;                            // segment id

    const int h = pix / W;
    const int w = pix - h * W;

    const float a = ((float)h - (H * 0.5f - 0.5f)) * (1.0f / FOCAL);
    const float b = -((float)w - (W * 0.5f - 0.5f)) * (1.0f / FOCAL);

    const float dx = a * s_cam[0] + b * s_cam[3] + s_cam[6];
    const float dy = a * s_cam[1] + b * s_cam[4] + s_cam[7];
    const float dz = a * s_cam[2] + b * s_cam[5] + s_cam[8];
    const float dn = sqrtf(dx * dx + dy * dy + dz * dz);

    const float px = s_cam[9], py = s_cam[10], pz = s_cam[11];

    float dirF[F], baseF[F];
    #pragma unroll
    for (int j = 0; j < F; j++) {
        dirF[j]  = dx * s_Wf[0][j] + dy * s_Wf[1][j] + dz * s_Wf[2][j];
        baseF[j] = px * s_Wf[0][j] + py * s_Wf[1][j] + pz * s_Wf[2][j] + s_bf[j];
    }
    const float dird  = dx * s_Wd3[0] + dy * s_Wd3[1] + dz * s_Wd3[2];
    const float based = px * s_Wd3[0] + py * s_Wd3[1] + pz * s_Wd3[2] + s_bd;

    float negBaseC[3];
    #pragma unroll
    for (int i = 0; i < 3; i++)
        negBaseC[i] = -(dx * s_Wc3[0][i] + dy * s_Wc3[1][i] + dz * s_Wc3[2][i] + s_bc[i]);

    // ---- local segment compositing (T starts at 1) ----
    float T = 1.0f;
    float c0 = 0.0f, c1 = 0.0f, c2 = 0.0f, depth = 0.0f;

    #pragma unroll 8
    for (int i = 0; i < SPT; i++) {
        const int xi = i * SEG + q;
        const float t = s_t[xi];

        float f[F];
        #pragma unroll
        for (int j = 0; j < F; j++)
            f[j] = fmaxf(fmaf(t, dirF[j], baseF[j]), 0.0f);

        float d = fmaf(t, dird, based);
        #pragma unroll
        for (int j = 0; j < F; j++)
            d = fmaf(f[j], s_WdF[j], d);
        d = fmaxf(d, 0.0f);

        const float e  = __expf(-d * (s_dl[xi] * dn));
        const float Tn = T * e;
        const float wgt = T - Tn;
        T = Tn;

        float x0 = negBaseC[0], x1 = negBaseC[1], x2 = negBaseC[2];
        #pragma unroll
        for (int j = 0; j < F; j++) {
            x0 = fmaf(f[j], s_negWcF[j][0], x0);
            x1 = fmaf(f[j], s_negWcF[j][1], x1);
            x2 = fmaf(f[j], s_negWcF[j][2], x2);
        }
        const float g0 = __fdividef(1.0f, 1.0f + __expf(x0));
        const float g1 = __fdividef(1.0f, 1.0f + __expf(x1));
        const float g2 = __fdividef(1.0f, 1.0f + __expf(x2));

        c0 = fmaf(wgt, g0, c0);
        c1 = fmaf(wgt, g1, c1);
        c2 = fmaf(wgt, g2, c2);
        depth += wgt;
    }

    // ---- segmented combine across the 4 threads of this pixel ----
    const unsigned mask = 0xFFFFFFFFu;
    const float T0 = __shfl_sync(mask, T, 0, 4);
    const float T1 = __shfl_sync(mask, T, 1, 4);
    const float T2 = __shfl_sync(mask, T, 2, 4);
    float p = 1.0f;
    if (q > 0) p *= T0;
    if (q > 1) p *= T1;
    if (q > 2) p *= T2;
    c0 *= p; c1 *= p; c2 *= p; depth *= p;

    #pragma unroll
    for (int off = 1; off < SEG; off <<= 1) {
        c0    += __shfl_xor_sync(mask, c0, off, 4);
        c1    += __shfl_xor_sync(mask, c1, off, 4);
        c2    += __shfl_xor_sync(mask, c2, off, 4);
        depth += __shfl_xor_sync(mask, depth, off, 4);
    }

    if (q == 0) {
        out[pix * 3 + 0] = c0;
        out[pix * 3 + 1] = c1;
        out[pix * 3 + 2] = c2;
        out[NPIX * 3 + pix] = depth;
    }
}

extern "C" void kernel_launch(void* const* d_in, const int* in_sizes, int n_in,
                              void* d_out, int out_size)
{
    const float* positions = (const float*)d_in[0];
    const float* forwards  = (const float*)d_in[1];
    const float* ups       = (const float*)d_in[2];
    const float* normal    = (const float*)d_in[3];
    const float* Wf        = (const float*)d_in[4];
    const float* bf        = (const float*)d_in[5];
    const float* Wd        = (const float*)d_in[6];
    const float* bd        = (const float*)d_in[7];
    const float* Wc        = (const float*)d_in[8];
    const float* bc        = (const float*)d_in[9];
    float* out = (float*)d_out;

    const int threads = 128;
    const int blocks = (NPIX * SEG) / threads;   // 1250
    render_kernel<<<blocks, threads>>>(positions, forwards, ups, normal,
                                       Wf, bf, Wd, bd, Wc, bc, out);
}